// round 7
// baseline (speedup 1.0000x reference)
#include <cuda_runtime.h>
#include <cstdint>

// RandomSaltPepper — bit-exact JAX threefry (partitionable path).
// R6: hybrid rotate. Rounds with rotation 26 (3 of 20 per threefry) compute the
// rotate on the FMA pipe: lo = x1 * 2^26 (mad.lo), hi = umulhi(x1, 2^26), then a
// single LOP3 merges (lo|hi)^x0. Per converted round: alu 2->1, fma 1->3.
// This moves the alu-pipe floor down to meet the issue floor (calibrated from
// R2/R6 ncu: fma pipe ~1.8x alu pipe throughput, issue 4/cyc/SM).
// All "adds" stay on the fma pipe via mad.lo.u32 with runtime one.

struct TFParams {
    // keys: [0]=k0 [1]=k1 [2]=ks2 [3]=ks2+1 [4]=k0+2 [5]=k1+3 [6]=ks2+4 [7]=k0+5 (mask)
    //       [8..15] same layout (color)
    uint32_t k[16];
};

// add forced onto the fma pipe: r = a*one + b (one == 1 at runtime)
__device__ __forceinline__ uint32_t madd(uint32_t a, uint32_t one, uint32_t b) {
    uint32_t r;
    asm("mad.lo.u32 %0, %1, %2, %3;" : "=r"(r) : "r"(a), "r"(one), "r"(b));
    return r;
}

// standard round: IMAD (fma) + SHF + LOP3 (alu)
__device__ __forceinline__ void tf_round(uint32_t& x0, uint32_t& x1, int r, uint32_t one) {
    x0 = madd(x1, one, x0);
    x1 = __funnelshift_l(x1, x1, r) ^ x0;
}

// converted round (rot 26): IMAD + mul.lo + mulhi (fma) + single LOP3 (alu)
// lo = x1<<26 (low 26 bits zero), hi = x1>>6 (high bits zero) -> lo|hi = rotl(x1,26)
__device__ __forceinline__ void tf_round_m(uint32_t& x0, uint32_t& x1,
                                           uint32_t mult, uint32_t one, uint32_t zero) {
    x0 = madd(x1, one, x0);
    uint32_t lo = madd(x1, mult, zero);      // IMAD (fma): x1 * 2^26
    uint32_t hi = __umulhi(x1, mult);        // IMAD.HI (fma): x1 >> 6
    x1 = (lo | hi) ^ x0;                     // single LOP3 (lut 0x54)
}

// threefry2x32, counter = (0, ctr), returns o0 ^ o1
__device__ __forceinline__ uint32_t tf_xor(const uint32_t* __restrict__ K,
                                           uint32_t ctr, uint32_t one,
                                           uint32_t m26, uint32_t zero) {
    uint32_t x0 = K[0];
    uint32_t x1 = madd(ctr, one, K[1]);
    tf_round(x0,x1,13,one); tf_round(x0,x1,15,one); tf_round_m(x0,x1,m26,one,zero); tf_round(x0,x1, 6,one);
    x0 = madd(K[1], one, x0);  x1 = madd(K[3], one, x1);   // += k1, += ks2+1
    tf_round(x0,x1,17,one); tf_round(x0,x1,29,one); tf_round(x0,x1,16,one); tf_round(x0,x1,24,one);
    x0 = madd(K[2], one, x0);  x1 = madd(K[4], one, x1);   // += ks2, += k0+2
    tf_round(x0,x1,13,one); tf_round(x0,x1,15,one); tf_round_m(x0,x1,m26,one,zero); tf_round(x0,x1, 6,one);
    x0 = madd(K[0], one, x0);  x1 = madd(K[5], one, x1);   // += k0,  += k1+3
    tf_round(x0,x1,17,one); tf_round(x0,x1,29,one); tf_round(x0,x1,16,one); tf_round(x0,x1,24,one);
    x0 = madd(K[1], one, x0);  x1 = madd(K[6], one, x1);   // += k1,  += ks2+4
    tf_round(x0,x1,13,one); tf_round(x0,x1,15,one); tf_round_m(x0,x1,m26,one,zero); tf_round(x0,x1, 6,one);
    x0 = madd(K[2], one, x0);  x1 = madd(K[7], one, x1);   // += ks2, += k0+5
    return x0 ^ x1;
}

// ---------------- host threefry2x32 (key derivation) ----------------
static void tf_round_h(uint32_t& x0, uint32_t& x1, int r) {
    x0 += x1;
    x1 = (x1 << r) | (x1 >> (32 - r));
    x1 ^= x0;
}
static void tf_host(uint32_t k0, uint32_t k1, uint32_t x0in, uint32_t x1in,
                    uint32_t& o0, uint32_t& o1) {
    uint32_t ks2 = k0 ^ k1 ^ 0x1BD11BDAu;
    uint32_t x0 = x0in + k0;
    uint32_t x1 = x1in + k1;
    tf_round_h(x0,x1,13); tf_round_h(x0,x1,15); tf_round_h(x0,x1,26); tf_round_h(x0,x1, 6);
    x0 += k1;  x1 += ks2 + 1u;
    tf_round_h(x0,x1,17); tf_round_h(x0,x1,29); tf_round_h(x0,x1,16); tf_round_h(x0,x1,24);
    x0 += ks2; x1 += k0 + 2u;
    tf_round_h(x0,x1,13); tf_round_h(x0,x1,15); tf_round_h(x0,x1,26); tf_round_h(x0,x1, 6);
    x0 += k0;  x1 += k1 + 3u;
    tf_round_h(x0,x1,17); tf_round_h(x0,x1,29); tf_round_h(x0,x1,16); tf_round_h(x0,x1,24);
    x0 += k1;  x1 += ks2 + 4u;
    tf_round_h(x0,x1,13); tf_round_h(x0,x1,15); tf_round_h(x0,x1,26); tf_round_h(x0,x1, 6);
    x0 += ks2; x1 += k0 + 5u;
    o0 = x0; o1 = x1;
}

// ---------------- kernel ----------------
// B=64, C=3, H=W=512. HW = 2^18, positions P = 2^24. 4 consecutive positions/thread.
__global__ __launch_bounds__(256, 1)
void RandomSaltPepper_9380208574641_kernel(
    const float4* __restrict__ in, float4* __restrict__ out,
    TFParams prm, uint32_t one, uint32_t two, uint32_t fone,
    uint32_t m26, uint32_t zero)
{
    const uint32_t* __restrict__ MK = prm.k;       // mask key block
    const uint32_t* __restrict__ CK = prm.k + 8;   // color key block

    uint32_t t  = blockIdx.x * blockDim.x + threadIdx.x;   // 0 .. 2^22-1
    uint32_t p0 = t << 2;                                  // base (b,h,w) index
    uint32_t b  = p0 >> 18;                                // batch
    uint32_t q4 = (p0 & 0x3FFFFu) >> 2;                    // float4 index within HW

    // hoist loads — latency hides under ~600 ALU/FMA instructions below
    uint32_t i0 = ((b * 3u + 0u) << 16) + q4;
    uint32_t i1 = i0 + (1u << 16);
    uint32_t i2 = i0 + (2u << 16);
    float4 v0 = in[i0];
    float4 v1 = in[i1];
    float4 v2 = in[i2];

    // z[i] = 1.0f if position keeps the image (mask false), else 0.0f
    // s[i] = 1.0f if masked AND salt, else 0.0f            out = v*z + s
    float z[4], s[4];
#pragma unroll
    for (int i = 0; i < 4; i++) {
        uint32_t bu = tf_xor(MK, p0 + i, one, m26, zero);
        uint32_t bc = tf_xor(CK, p0 + i, one, m26, zero);
        uint32_t tb = __umulhi(bu, two);               // bit31(bu): 1 = keep image (fma)
        uint32_t sb = (~tb) & (~bc) & 1u;              // masked & salt (one LOP3)
        z[i] = __uint_as_float(tb * fone);             // IMAD (fma): 0x3F800000 or 0
        s[i] = __uint_as_float(sb * fone);             // IMAD (fma)
    }

    float4 o0, o1, o2;
    o0.x = fmaf(v0.x, z[0], s[0]);  o0.y = fmaf(v0.y, z[1], s[1]);
    o0.z = fmaf(v0.z, z[2], s[2]);  o0.w = fmaf(v0.w, z[3], s[3]);
    o1.x = fmaf(v1.x, z[0], s[0]);  o1.y = fmaf(v1.y, z[1], s[1]);
    o1.z = fmaf(v1.z, z[2], s[2]);  o1.w = fmaf(v1.w, z[3], s[3]);
    o2.x = fmaf(v2.x, z[0], s[0]);  o2.y = fmaf(v2.y, z[1], s[1]);
    o2.z = fmaf(v2.z, z[2], s[2]);  o2.w = fmaf(v2.w, z[3], s[3]);
    out[i0] = o0;
    out[i1] = o1;
    out[i2] = o2;
}

extern "C" void kernel_launch(void* const* d_in, const int* in_sizes, int n_in,
                              void* d_out, int out_size)
{
    const float4* in  = (const float4*)d_in[0];
    float4*       out = (float4*)d_out;

    // ---- derive JAX keys on host ----
    uint32_t k1a, k1b, k2a, k2b;
    tf_host(0u, 42u, 0u, 0u, k1a, k1b);          // k1 = split(root)[0]
    tf_host(0u, 42u, 0u, 1u, k2a, k2b);          // k2 = split(root)[1]
    uint32_t kb0, kb1;
    tf_host(k2a, k2b, 0u, 1u, kb0, kb1);         // randint internal split, child 1

    TFParams prm;
    {
        uint32_t k0 = k1a, k1 = k1b, ks2 = k0 ^ k1 ^ 0x1BD11BDAu;
        uint32_t* K = prm.k;
        K[0]=k0; K[1]=k1; K[2]=ks2; K[3]=ks2+1u; K[4]=k0+2u; K[5]=k1+3u; K[6]=ks2+4u; K[7]=k0+5u;
    }
    {
        uint32_t k0 = kb0, k1 = kb1, ks2 = k0 ^ k1 ^ 0x1BD11BDAu;
        uint32_t* K = prm.k + 8;
        K[0]=k0; K[1]=k1; K[2]=ks2; K[3]=ks2+1u; K[4]=k0+2u; K[5]=k1+3u; K[6]=ks2+4u; K[7]=k0+5u;
    }

    const int threads = 256;
    const int blocks  = (1 << 22) / threads;     // 16384
    RandomSaltPepper_9380208574641_kernel<<<blocks, threads>>>(
        in, out, prm, 1u, 2u, 0x3F800000u, 1u << 26, 0u);
}